// round 2
// baseline (speedup 1.0000x reference)
#include <cuda_runtime.h>
#include <cuda_bf16.h>
#include <math.h>

#define MAXN 50000
#define MAXE 800000
#define F1 64      // nfeat
#define F2 128     // nhid
#define F3 64      // nclass
#define EPS 1e-6f

// ---------------- scratch (no allocation allowed) ----------------
__device__ __align__(16) float g_num1[MAXN * F1];   // 12.8 MB
__device__ __align__(16) float g_h[MAXN * F2];      // 25.6 MB
__device__ __align__(16) float g_num2[MAXN * F2];   // 25.6 MB
__device__ float g_deg[MAXN];

// ---------------- aggregation: scatter-add feat[src] into out[dst] ----------------
// One thread per (edge, float4-chunk). FVEC = feats/4.
template <int FVEC, bool ADD_DEG>
__global__ void agg_kernel(const float* __restrict__ feat,
                           const int* __restrict__ src,
                           const int* __restrict__ dst,
                           float* __restrict__ out,
                           float* __restrict__ deg,
                           int E)
{
    int idx = blockIdx.x * blockDim.x + threadIdx.x;
    int total = E * FVEC;
    if (idx >= total) return;
    int e = idx / FVEC;
    int c = idx - e * FVEC;
    int s = __ldg(src + e);
    int d = __ldg(dst + e);
    float4 v = reinterpret_cast<const float4*>(feat)[s * FVEC + c];
    float* p = out + ((long)d * FVEC + c) * 4;
    asm volatile("red.global.add.v4.f32 [%0], {%1,%2,%3,%4};"
                 :: "l"(p), "f"(v.x), "f"(v.y), "f"(v.z), "f"(v.w) : "memory");
    if (ADD_DEG && c == 0) atomicAdd(deg + d, 1.0f);
}

// ---------------- GEMM1: h = relu(mean1 @ W1 + b1) ----------------
// Block: 256 threads, 16 nodes. W1 [64,128] in smem (32KB) + mean rows (4KB).
__global__ __launch_bounds__(256) void gemm1_kernel(const float* __restrict__ num1,
                                                    const float* __restrict__ deg,
                                                    const float* __restrict__ W1,
                                                    const float* __restrict__ b1,
                                                    float* __restrict__ h,
                                                    int N)
{
    __shared__ float Ws[F1 * F2];      // 32 KB
    __shared__ float Ms[16 * F1];      // 4 KB
    int tid = threadIdx.x;
    int node0 = blockIdx.x * 16;

    for (int i = tid; i < F1 * F2; i += 256) Ws[i] = W1[i];
    for (int i = tid; i < 16 * F1; i += 256) {
        int n = i / F1;
        int node = node0 + n;
        float m = 0.0f;
        if (node < N) {
            float dg = deg[node] + EPS;
            m = num1[node * F1 + (i - n * F1)] / dg;
        }
        Ms[i] = m;
    }
    __syncthreads();

    int col  = tid & 127;        // 0..127
    int half = tid >> 7;         // 0..1 -> nodes half*8 .. half*8+7
    float acc[8];
    float bias = b1[col];
    #pragma unroll
    for (int i = 0; i < 8; i++) acc[i] = bias;
    #pragma unroll 8
    for (int k = 0; k < F1; k++) {
        float w = Ws[k * F2 + col];
        #pragma unroll
        for (int i = 0; i < 8; i++)
            acc[i] = fmaf(Ms[(half * 8 + i) * F1 + k], w, acc[i]);
    }
    #pragma unroll
    for (int i = 0; i < 8; i++) {
        int node = node0 + half * 8 + i;
        if (node < N) h[node * F2 + col] = fmaxf(acc[i], 0.0f);
    }
}

// ---------------- GEMM2 + log_softmax ----------------
// Block: 256 threads, 16 nodes. W2 [128,64] smem 32KB + mean rows 8KB + logits 4KB.
__global__ __launch_bounds__(256) void gemm2_kernel(const float* __restrict__ num2,
                                                    const float* __restrict__ deg,
                                                    const float* __restrict__ W2,
                                                    const float* __restrict__ b2,
                                                    float* __restrict__ out,
                                                    int N)
{
    __shared__ float Ws[F2 * F3];      // 32 KB
    __shared__ float Ms[16 * F2];      // 8 KB
    __shared__ float Ls[16 * F3];      // 4 KB
    int tid = threadIdx.x;
    int node0 = blockIdx.x * 16;

    for (int i = tid; i < F2 * F3; i += 256) Ws[i] = W2[i];
    for (int i = tid; i < 16 * F2; i += 256) {
        int n = i / F2;
        int node = node0 + n;
        float m = 0.0f;
        if (node < N) {
            float dg = deg[node] + EPS;
            m = num2[node * F2 + (i - n * F2)] / dg;
        }
        Ms[i] = m;
    }
    __syncthreads();

    int col = tid & 63;          // 0..63
    int grp = tid >> 6;          // 0..3 -> nodes grp*4 .. grp*4+3
    float acc[4];
    float bias = b2[col];
    #pragma unroll
    for (int i = 0; i < 4; i++) acc[i] = bias;
    #pragma unroll 8
    for (int k = 0; k < F2; k++) {
        float w = Ws[k * F3 + col];
        #pragma unroll
        for (int i = 0; i < 4; i++)
            acc[i] = fmaf(Ms[(grp * 4 + i) * F2 + k], w, acc[i]);
    }
    #pragma unroll
    for (int i = 0; i < 4; i++)
        Ls[(grp * 4 + i) * F3 + col] = acc[i];
    __syncthreads();

    // log_softmax: one warp per node, 8 warps x 2 nodes each.
    int wid = tid >> 5;
    int lane = tid & 31;
    #pragma unroll
    for (int rep = 0; rep < 2; rep++) {
        int n = wid + rep * 8;
        int node = node0 + n;
        float v0 = Ls[n * F3 + lane];
        float v1 = Ls[n * F3 + lane + 32];
        float m = fmaxf(v0, v1);
        #pragma unroll
        for (int o = 16; o > 0; o >>= 1)
            m = fmaxf(m, __shfl_xor_sync(0xffffffffu, m, o));
        float s = expf(v0 - m) + expf(v1 - m);
        #pragma unroll
        for (int o = 16; o > 0; o >>= 1)
            s += __shfl_xor_sync(0xffffffffu, s, o);
        float l = m + logf(s);
        if (node < N) {
            out[node * F3 + lane]      = v0 - l;
            out[node * F3 + lane + 32] = v1 - l;
        }
    }
}

extern "C" void kernel_launch(void* const* d_in, const int* in_sizes, int n_in,
                              void* d_out, int out_size)
{
    const float* x   = (const float*)d_in[0];
    const int*   src = (const int*)d_in[1];
    const int*   dst = (const int*)d_in[2];
    const float* W1  = (const float*)d_in[3];
    const float* b1  = (const float*)d_in[4];
    const float* W2  = (const float*)d_in[5];
    const float* b2  = (const float*)d_in[6];
    float* out = (float*)d_out;

    int N = in_sizes[0] / F1;
    int E = in_sizes[1];

    float *num1, *num2, *deg, *h;
    cudaGetSymbolAddress((void**)&num1, g_num1);
    cudaGetSymbolAddress((void**)&num2, g_num2);
    cudaGetSymbolAddress((void**)&deg,  g_deg);
    cudaGetSymbolAddress((void**)&h,    g_h);

    cudaMemsetAsync(num1, 0, (size_t)N * F1 * sizeof(float), 0);
    cudaMemsetAsync(num2, 0, (size_t)N * F2 * sizeof(float), 0);
    cudaMemsetAsync(deg,  0, (size_t)N * sizeof(float), 0);

    {   // aggregation 1 (+ degree)
        int total = E * (F1 / 4);
        int blocks = (total + 255) / 256;
        agg_kernel<F1 / 4, true><<<blocks, 256, 0, 0>>>(x, src, dst, num1, deg, E);
    }
    {   // gemm1 + relu
        int blocks = (N + 15) / 16;
        gemm1_kernel<<<blocks, 256, 0, 0>>>(num1, deg, W1, b1, h, N);
    }
    {   // aggregation 2
        int total = E * (F2 / 4);
        int blocks = (total + 255) / 256;
        agg_kernel<F2 / 4, false><<<blocks, 256, 0, 0>>>(h, src, dst, num2, deg, E);
    }
    {   // gemm2 + log_softmax
        int blocks = (N + 15) / 16;
        gemm2_kernel<<<blocks, 256, 0, 0>>>(num2, deg, W2, b2, out, N);
    }
}

// round 3
// speedup vs baseline: 1.5827x; 1.5827x over previous
#include <cuda_runtime.h>
#include <cuda_bf16.h>
#include <math.h>

#define MAXN 50000
#define F1 64      // nfeat
#define F2 128     // nhid
#define F3 64      // nclass
#define EPS 1e-6f

// ---------------- scratch (no allocation allowed) ----------------
__device__ __align__(16) float g_num1[MAXN * F1];   // 12.8 MB: segsum(x[src])
__device__ __align__(16) float g_h[MAXN * F2];      // 25.6 MB: relu layer-1 out
__device__ __align__(16) float g_t[MAXN * F3];      // 12.8 MB: h @ W2
__device__ __align__(16) float g_num2[MAXN * F3];   // 12.8 MB: segsum(t[src])
__device__ float g_deg[MAXN];

// ---------------- aggregation: scatter-add feat[src] into out[dst] ----------------
// One thread per (edge, float4-chunk). FVEC = feats/4.
template <int FVEC, bool ADD_DEG>
__global__ void agg_kernel(const float* __restrict__ feat,
                           const int* __restrict__ src,
                           const int* __restrict__ dst,
                           float* __restrict__ out,
                           float* __restrict__ deg,
                           int E)
{
    int idx = blockIdx.x * blockDim.x + threadIdx.x;
    int total = E * FVEC;
    if (idx >= total) return;
    int e = idx / FVEC;
    int c = idx - e * FVEC;
    int s = __ldg(src + e);
    int d = __ldg(dst + e);
    float4 v = reinterpret_cast<const float4*>(feat)[s * FVEC + c];
    float* p = out + ((long)d * FVEC + c) * 4;
    asm volatile("red.global.add.v4.f32 [%0], {%1,%2,%3,%4};"
                 :: "l"(p), "f"(v.x), "f"(v.y), "f"(v.z), "f"(v.w) : "memory");
    if (ADD_DEG && c == 0) atomicAdd(deg + d, 1.0f);
}

// ---------------- GEMM1: h = relu((num1/deg) @ W1 + b1) ----------------
// Block tile 64x128 (full N-dim), K=64 full. 256 threads, each 8 rows x 4 cols.
__global__ __launch_bounds__(256) void gemm1_kernel(const float* __restrict__ num1,
                                                    const float* __restrict__ deg,
                                                    const float* __restrict__ W1,
                                                    const float* __restrict__ b1,
                                                    float* __restrict__ h,
                                                    int N)
{
    __shared__ float As[64][64];      // 16 KB, mean rows
    __shared__ float Ws[64][128];     // 32 KB
    int tid = threadIdx.x;
    int node0 = blockIdx.x * 64;

    // load W1: 8192 floats = 2048 float4, 8 per thread
    #pragma unroll
    for (int i = 0; i < 8; i++) {
        int lin = tid + i * 256;
        ((float4*)Ws)[lin] = ((const float4*)W1)[lin];
    }
    // load mean tile: 4096 floats = 1024 float4, 4 per thread (divide by degree here)
    #pragma unroll
    for (int i = 0; i < 4; i++) {
        int lin = tid + i * 256;
        int row = lin >> 4;          // 16 float4 per row
        int kq  = lin & 15;
        int node = node0 + row;
        float4 v = make_float4(0.f, 0.f, 0.f, 0.f);
        if (node < N) {
            v = ((const float4*)num1)[node * 16 + kq];
            float inv = 1.0f / (deg[node] + EPS);
            v.x *= inv; v.y *= inv; v.z *= inv; v.w *= inv;
        }
        ((float4*)As)[lin] = v;
    }
    __syncthreads();

    int tx = tid & 31, ty = tid >> 5;
    int col0 = tx * 4, row0 = ty * 8;
    float4 acc[8];
    float4 bias = *(const float4*)(b1 + col0);
    #pragma unroll
    for (int r = 0; r < 8; r++) acc[r] = bias;

    #pragma unroll 4
    for (int k = 0; k < 64; k++) {
        float4 w = *(float4*)&Ws[k][col0];
        #pragma unroll
        for (int r = 0; r < 8; r++) {
            float m = As[row0 + r][k];       // broadcast within warp
            acc[r].x = fmaf(m, w.x, acc[r].x);
            acc[r].y = fmaf(m, w.y, acc[r].y);
            acc[r].z = fmaf(m, w.z, acc[r].z);
            acc[r].w = fmaf(m, w.w, acc[r].w);
        }
    }

    #pragma unroll
    for (int r = 0; r < 8; r++) {
        int node = node0 + row0 + r;
        if (node < N) {
            float4 o;
            o.x = fmaxf(acc[r].x, 0.f);
            o.y = fmaxf(acc[r].y, 0.f);
            o.z = fmaxf(acc[r].z, 0.f);
            o.w = fmaxf(acc[r].w, 0.f);
            *(float4*)(h + node * F2 + col0) = o;
        }
    }
}

// ---------------- GEMM2a: t = h @ W2 (no bias, no mean — both commute past segsum) ----
// Block tile 64x64, K=128 in two 64-chunks. 256 threads, each 4 rows x 4 cols.
__global__ __launch_bounds__(256) void gemm2a_kernel(const float* __restrict__ h,
                                                     const float* __restrict__ W2,
                                                     float* __restrict__ t,
                                                     int N)
{
    __shared__ float Ws[128][64];     // 32 KB, full W2
    __shared__ float As[64][64];      // 16 KB, K-chunk of h
    int tid = threadIdx.x;
    int node0 = blockIdx.x * 64;

    // load W2: 8192 floats = 2048 float4, 8 per thread
    #pragma unroll
    for (int i = 0; i < 8; i++) {
        int lin = tid + i * 256;
        ((float4*)Ws)[lin] = ((const float4*)W2)[lin];
    }

    int tx = tid & 15, ty = tid >> 4;
    int col0 = tx * 4, row0 = ty * 4;
    float4 acc[4];
    #pragma unroll
    for (int r = 0; r < 4; r++) acc[r] = make_float4(0.f, 0.f, 0.f, 0.f);

    #pragma unroll
    for (int kc = 0; kc < 128; kc += 64) {
        __syncthreads();   // protect As from previous chunk's readers (and Ws 1st iter)
        #pragma unroll
        for (int i = 0; i < 4; i++) {
            int lin = tid + i * 256;
            int row = lin >> 4;
            int kq  = lin & 15;
            int node = node0 + row;
            float4 v = make_float4(0.f, 0.f, 0.f, 0.f);
            if (node < N)
                v = ((const float4*)h)[node * 32 + (kc >> 2) + kq];
            ((float4*)As)[lin] = v;
        }
        __syncthreads();

        #pragma unroll 4
        for (int k = 0; k < 64; k++) {
            float4 w = *(float4*)&Ws[kc + k][col0];
            #pragma unroll
            for (int r = 0; r < 4; r++) {
                float m = As[row0 + r][k];
                acc[r].x = fmaf(m, w.x, acc[r].x);
                acc[r].y = fmaf(m, w.y, acc[r].y);
                acc[r].z = fmaf(m, w.z, acc[r].z);
                acc[r].w = fmaf(m, w.w, acc[r].w);
            }
        }
    }

    #pragma unroll
    for (int r = 0; r < 4; r++) {
        int node = node0 + row0 + r;
        if (node < N)
            *(float4*)(t + node * F3 + col0) = acc[r];
    }
}

// ---------------- Final: out = log_softmax(num2/deg + b2) ----------------
// One warp per node, 2 cols per lane.
__global__ __launch_bounds__(256) void final_kernel(const float* __restrict__ num2,
                                                    const float* __restrict__ deg,
                                                    const float* __restrict__ b2,
                                                    float* __restrict__ out,
                                                    int N)
{
    int node = (blockIdx.x * blockDim.x + threadIdx.x) >> 5;
    int lane = threadIdx.x & 31;
    if (node >= N) return;
    float inv = 1.0f / (deg[node] + EPS);
    float v0 = num2[node * F3 + lane]      * inv + b2[lane];
    float v1 = num2[node * F3 + lane + 32] * inv + b2[lane + 32];
    float m = fmaxf(v0, v1);
    #pragma unroll
    for (int o = 16; o > 0; o >>= 1)
        m = fmaxf(m, __shfl_xor_sync(0xffffffffu, m, o));
    float s = expf(v0 - m) + expf(v1 - m);
    #pragma unroll
    for (int o = 16; o > 0; o >>= 1)
        s += __shfl_xor_sync(0xffffffffu, s, o);
    float l = m + logf(s);
    out[node * F3 + lane]      = v0 - l;
    out[node * F3 + lane + 32] = v1 - l;
}

extern "C" void kernel_launch(void* const* d_in, const int* in_sizes, int n_in,
                              void* d_out, int out_size)
{
    const float* x   = (const float*)d_in[0];
    const int*   src = (const int*)d_in[1];
    const int*   dst = (const int*)d_in[2];
    const float* W1  = (const float*)d_in[3];
    const float* b1  = (const float*)d_in[4];
    const float* W2  = (const float*)d_in[5];
    const float* b2  = (const float*)d_in[6];
    float* out = (float*)d_out;

    int N = in_sizes[0] / F1;
    int E = in_sizes[1];

    float *num1, *num2, *deg, *h, *t;
    cudaGetSymbolAddress((void**)&num1, g_num1);
    cudaGetSymbolAddress((void**)&num2, g_num2);
    cudaGetSymbolAddress((void**)&deg,  g_deg);
    cudaGetSymbolAddress((void**)&h,    g_h);
    cudaGetSymbolAddress((void**)&t,    g_t);

    cudaMemsetAsync(num1, 0, (size_t)N * F1 * sizeof(float), 0);
    cudaMemsetAsync(num2, 0, (size_t)N * F3 * sizeof(float), 0);
    cudaMemsetAsync(deg,  0, (size_t)N * sizeof(float), 0);

    {   // aggregation 1 (64-wide, + degree)
        int total = E * (F1 / 4);
        int blocks = (total + 255) / 256;
        agg_kernel<F1 / 4, true><<<blocks, 256, 0, 0>>>(x, src, dst, num1, deg, E);
    }
    {   // gemm1: mean + W1 + b1 + relu -> h
        int blocks = (N + 63) / 64;
        gemm1_kernel<<<blocks, 256, 0, 0>>>(num1, deg, W1, b1, h, N);
    }
    {   // gemm2a: t = h @ W2 (transform BEFORE aggregation: 128-wide -> 64-wide)
        int blocks = (N + 63) / 64;
        gemm2a_kernel<<<blocks, 256, 0, 0>>>(h, W2, t, N);
    }
    {   // aggregation 2 (64-wide now, half the atomic traffic)
        int total = E * (F3 / 4);
        int blocks = (total + 255) / 256;
        agg_kernel<F3 / 4, false><<<blocks, 256, 0, 0>>>(t, src, dst, num2, deg, E);
    }
    {   // mean + bias + log_softmax
        int blocks = (N * 32 + 255) / 256;
        final_kernel<<<blocks, 256, 0, 0>>>(num2, deg, b2, out, N);
    }
}

// round 4
// speedup vs baseline: 1.8684x; 1.1806x over previous
#include <cuda_runtime.h>
#include <cuda_bf16.h>
#include <math.h>

#define MAXN 50000
#define MAXE 800000
#define F1 64      // nfeat
#define F2 128     // nhid
#define F3 64      // nclass
#define EPS 1e-6f

// ---------------- scratch (no allocation allowed) ----------------
__device__ __align__(16) float g_h[MAXN * F2];      // 25.6 MB: relu layer-1 out
__device__ __align__(16) float g_t[MAXN * F3];      // 12.8 MB: h @ W2
__device__ int g_counts[MAXN];                       // per-dst degree (int)
__device__ int g_rowptr[MAXN + 1];
__device__ int g_cursor[MAXN];
__device__ int g_partials[64];
__device__ int g_sorted_src[MAXE];                   // src ids grouped by dst

// ================= CSR build =================
__global__ void hist_kernel(const int* __restrict__ dst, int* __restrict__ counts, int E)
{
    int i = blockIdx.x * blockDim.x + threadIdx.x;
    if (i < E) atomicAdd(counts + __ldg(dst + i), 1);
}

// block = 256 threads, 1024 elements per block
__global__ void scan1_kernel(const int* __restrict__ counts, int* __restrict__ rowptr,
                             int* __restrict__ partials, int N)
{
    __shared__ int s[256];
    int b = blockIdx.x, t = threadIdx.x;
    int base = b * 1024 + t * 4;
    int v[4]; int sum = 0;
    #pragma unroll
    for (int j = 0; j < 4; j++) {
        v[j] = (base + j < N) ? counts[base + j] : 0;
        sum += v[j];
    }
    s[t] = sum;
    __syncthreads();
    #pragma unroll
    for (int off = 1; off < 256; off <<= 1) {
        int x = (t >= off) ? s[t - off] : 0;
        __syncthreads();
        s[t] += x;
        __syncthreads();
    }
    int run = s[t] - sum;              // exclusive prefix of this thread's 4
    if (t == 255) partials[b] = s[255];
    #pragma unroll
    for (int j = 0; j < 4; j++) {
        if (base + j < N) rowptr[base + j] = run;
        run += v[j];
    }
}

__global__ void scan2_kernel(int* __restrict__ partials, int nb)
{
    if (threadIdx.x == 0 && blockIdx.x == 0) {
        int acc = 0;
        for (int i = 0; i < nb; i++) { int p = partials[i]; partials[i] = acc; acc += p; }
    }
}

__global__ void scan3_kernel(int* __restrict__ rowptr, const int* __restrict__ partials,
                             int* __restrict__ cursor, int N, int E)
{
    int i = blockIdx.x * blockDim.x + threadIdx.x;
    if (i < N) {
        int r = rowptr[i] + partials[i >> 10];
        rowptr[i] = r;
        cursor[i] = r;
    }
    if (i == 0) rowptr[N] = E;
}

__global__ void scatter_kernel(const int* __restrict__ src, const int* __restrict__ dst,
                               int* __restrict__ cursor, int* __restrict__ sorted_src, int E)
{
    int i = blockIdx.x * blockDim.x + threadIdx.x;
    if (i < E) {
        int pos = atomicAdd(cursor + __ldg(dst + i), 1);
        sorted_src[pos] = __ldg(src + i);
    }
}

// ================= GEMM1 fused with gather-1 =================
// Block tile: 64 nodes x 128 cols. Each of 8 warps gathers 8 node rows
// (CSR mean over x) straight into As, then register-tiled GEMM + relu.
__global__ __launch_bounds__(256) void gemm1_fused_kernel(const float* __restrict__ x,
                                                          const int* __restrict__ rowptr,
                                                          const int* __restrict__ sorted_src,
                                                          const float* __restrict__ W1,
                                                          const float* __restrict__ b1,
                                                          float* __restrict__ h,
                                                          int N)
{
    __shared__ float As[64][64];      // 16 KB, mean rows
    __shared__ float Ws[64][128];     // 32 KB
    int tid = threadIdx.x;
    int node0 = blockIdx.x * 64;
    int wid = tid >> 5, lane = tid & 31;

    // load W1: 8192 floats = 2048 float4, 8 per thread
    #pragma unroll
    for (int i = 0; i < 8; i++) {
        int lin = tid + i * 256;
        ((float4*)Ws)[lin] = ((const float4*)W1)[lin];
    }

    // gather: warp w handles tile rows w*8..w*8+7; lane owns 2 contiguous cols
    #pragma unroll
    for (int r = 0; r < 8; r++) {
        int row = wid * 8 + r;
        int node = node0 + row;
        float2 acc = make_float2(0.f, 0.f);
        if (node < N) {
            int beg = __ldg(rowptr + node);
            int end = __ldg(rowptr + node + 1);
            #pragma unroll 4
            for (int e = beg; e < end; e++) {
                int s = __ldg(sorted_src + e);
                float2 v = ((const float2*)x)[s * 32 + lane];
                acc.x += v.x; acc.y += v.y;
            }
            float inv = 1.0f / ((float)(end - beg) + EPS);
            acc.x *= inv; acc.y *= inv;
        }
        *(float2*)&As[row][lane * 2] = acc;
    }
    __syncthreads();

    int tx = tid & 31, ty = tid >> 5;
    int col0 = tx * 4, row0 = ty * 8;
    float4 acc[8];
    float4 bias = *(const float4*)(b1 + col0);
    #pragma unroll
    for (int r = 0; r < 8; r++) acc[r] = bias;

    #pragma unroll 4
    for (int k = 0; k < 64; k++) {
        float4 w = *(float4*)&Ws[k][col0];
        #pragma unroll
        for (int r = 0; r < 8; r++) {
            float m = As[row0 + r][k];
            acc[r].x = fmaf(m, w.x, acc[r].x);
            acc[r].y = fmaf(m, w.y, acc[r].y);
            acc[r].z = fmaf(m, w.z, acc[r].z);
            acc[r].w = fmaf(m, w.w, acc[r].w);
        }
    }

    #pragma unroll
    for (int r = 0; r < 8; r++) {
        int node = node0 + row0 + r;
        if (node < N) {
            float4 o;
            o.x = fmaxf(acc[r].x, 0.f);
            o.y = fmaxf(acc[r].y, 0.f);
            o.z = fmaxf(acc[r].z, 0.f);
            o.w = fmaxf(acc[r].w, 0.f);
            *(float4*)(h + node * F2 + col0) = o;
        }
    }
}

// ================= GEMM2a: t = h @ W2 =================
__global__ __launch_bounds__(256) void gemm2a_kernel(const float* __restrict__ h,
                                                     const float* __restrict__ W2,
                                                     float* __restrict__ t,
                                                     int N)
{
    __shared__ float Ws[128][64];     // 32 KB, full W2
    __shared__ float As[64][64];      // 16 KB, K-chunk of h
    int tid = threadIdx.x;
    int node0 = blockIdx.x * 64;

    #pragma unroll
    for (int i = 0; i < 8; i++) {
        int lin = tid + i * 256;
        ((float4*)Ws)[lin] = ((const float4*)W2)[lin];
    }

    int tx = tid & 15, ty = tid >> 4;
    int col0 = tx * 4, row0 = ty * 4;
    float4 acc[4];
    #pragma unroll
    for (int r = 0; r < 4; r++) acc[r] = make_float4(0.f, 0.f, 0.f, 0.f);

    #pragma unroll
    for (int kc = 0; kc < 128; kc += 64) {
        __syncthreads();
        #pragma unroll
        for (int i = 0; i < 4; i++) {
            int lin = tid + i * 256;
            int row = lin >> 4;
            int kq  = lin & 15;
            int node = node0 + row;
            float4 v = make_float4(0.f, 0.f, 0.f, 0.f);
            if (node < N)
                v = ((const float4*)h)[node * 32 + (kc >> 2) + kq];
            ((float4*)As)[lin] = v;
        }
        __syncthreads();

        #pragma unroll 4
        for (int k = 0; k < 64; k++) {
            float4 w = *(float4*)&Ws[kc + k][col0];
            #pragma unroll
            for (int r = 0; r < 4; r++) {
                float m = As[row0 + r][k];
                acc[r].x = fmaf(m, w.x, acc[r].x);
                acc[r].y = fmaf(m, w.y, acc[r].y);
                acc[r].z = fmaf(m, w.z, acc[r].z);
                acc[r].w = fmaf(m, w.w, acc[r].w);
            }
        }
    }

    #pragma unroll
    for (int r = 0; r < 4; r++) {
        int node = node0 + row0 + r;
        if (node < N)
            *(float4*)(t + node * F3 + col0) = acc[r];
    }
}

// ================= gather-2 + bias + log_softmax =================
// One warp per node; lane owns cols 2*lane, 2*lane+1.
__global__ __launch_bounds__(256) void gather2_final_kernel(const float* __restrict__ t,
                                                            const int* __restrict__ rowptr,
                                                            const int* __restrict__ sorted_src,
                                                            const float* __restrict__ b2,
                                                            float* __restrict__ out,
                                                            int N)
{
    int node = (blockIdx.x * blockDim.x + threadIdx.x) >> 5;
    int lane = threadIdx.x & 31;
    if (node >= N) return;

    int beg = __ldg(rowptr + node);
    int end = __ldg(rowptr + node + 1);
    float2 acc = make_float2(0.f, 0.f);
    #pragma unroll 4
    for (int e = beg; e < end; e++) {
        int s = __ldg(sorted_src + e);
        float2 v = ((const float2*)t)[s * 32 + lane];
        acc.x += v.x; acc.y += v.y;
    }
    float inv = 1.0f / ((float)(end - beg) + EPS);
    float2 bb = ((const float2*)b2)[lane];
    float v0 = acc.x * inv + bb.x;
    float v1 = acc.y * inv + bb.y;

    float m = fmaxf(v0, v1);
    #pragma unroll
    for (int o = 16; o > 0; o >>= 1)
        m = fmaxf(m, __shfl_xor_sync(0xffffffffu, m, o));
    float s = expf(v0 - m) + expf(v1 - m);
    #pragma unroll
    for (int o = 16; o > 0; o >>= 1)
        s += __shfl_xor_sync(0xffffffffu, s, o);
    float l = m + logf(s);

    float2 o2 = make_float2(v0 - l, v1 - l);
    ((float2*)out)[node * 32 + lane] = o2;
}

extern "C" void kernel_launch(void* const* d_in, const int* in_sizes, int n_in,
                              void* d_out, int out_size)
{
    const float* x   = (const float*)d_in[0];
    const int*   src = (const int*)d_in[1];
    const int*   dst = (const int*)d_in[2];
    const float* W1  = (const float*)d_in[3];
    const float* b1  = (const float*)d_in[4];
    const float* W2  = (const float*)d_in[5];
    const float* b2  = (const float*)d_in[6];
    float* out = (float*)d_out;

    int N = in_sizes[0] / F1;
    int E = in_sizes[1];

    float *h, *t;
    int *counts, *rowptr, *cursor, *partials, *sorted_src;
    cudaGetSymbolAddress((void**)&h, g_h);
    cudaGetSymbolAddress((void**)&t, g_t);
    cudaGetSymbolAddress((void**)&counts, g_counts);
    cudaGetSymbolAddress((void**)&rowptr, g_rowptr);
    cudaGetSymbolAddress((void**)&cursor, g_cursor);
    cudaGetSymbolAddress((void**)&partials, g_partials);
    cudaGetSymbolAddress((void**)&sorted_src, g_sorted_src);

    // ---- CSR build ----
    cudaMemsetAsync(counts, 0, (size_t)N * sizeof(int), 0);
    hist_kernel<<<(E + 255) / 256, 256, 0, 0>>>(dst, counts, E);
    int nb = (N + 1023) / 1024;
    scan1_kernel<<<nb, 256, 0, 0>>>(counts, rowptr, partials, N);
    scan2_kernel<<<1, 32, 0, 0>>>(partials, nb);
    scan3_kernel<<<(N + 255) / 256, 256, 0, 0>>>(rowptr, partials, cursor, N, E);
    scatter_kernel<<<(E + 255) / 256, 256, 0, 0>>>(src, dst, cursor, sorted_src, E);

    // ---- layer 1: gather(mean) + W1 + b1 + relu ----
    gemm1_fused_kernel<<<(N + 63) / 64, 256, 0, 0>>>(x, rowptr, sorted_src, W1, b1, h, N);

    // ---- t = h @ W2 (transform before aggregation) ----
    gemm2a_kernel<<<(N + 63) / 64, 256, 0, 0>>>(h, W2, t, N);

    // ---- layer 2: gather(mean) + b2 + log_softmax ----
    gather2_final_kernel<<<(N * 32 + 255) / 256, 256, 0, 0>>>(t, rowptr, sorted_src, b2, out, N);
}

// round 5
// speedup vs baseline: 2.1365x; 1.1435x over previous
#include <cuda_runtime.h>
#include <cuda_bf16.h>
#include <math.h>

#define MAXN 50000
#define MAXE 800000
#define F1 64      // nfeat
#define F2 128     // nhid
#define F3 64      // nclass
#define EPS 1e-6f

// ---------------- scratch (no allocation allowed) ----------------
__device__ __align__(16) float g_h[MAXN * F2];      // 25.6 MB: relu layer-1 out
__device__ __align__(16) float g_t[MAXN * F3];      // 12.8 MB: h @ W2
__device__ int g_counts[MAXN];
__device__ int g_rowptr[MAXN + 1];
__device__ int g_cursor[MAXN];
__device__ int g_partials[64];
__device__ int g_sorted_src[MAXE];                   // src ids grouped by dst

// ================= CSR build =================
__global__ void hist_kernel(const int* __restrict__ dst, int* __restrict__ counts, int E)
{
    int i = blockIdx.x * blockDim.x + threadIdx.x;
    if (i < E) atomicAdd(counts + __ldg(dst + i), 1);
}

// block = 256 threads, 1024 elements per block
__global__ void scan1_kernel(const int* __restrict__ counts, int* __restrict__ rowptr,
                             int* __restrict__ partials, int N)
{
    __shared__ int s[256];
    int b = blockIdx.x, t = threadIdx.x;
    int base = b * 1024 + t * 4;
    int v[4]; int sum = 0;
    #pragma unroll
    for (int j = 0; j < 4; j++) {
        v[j] = (base + j < N) ? counts[base + j] : 0;
        sum += v[j];
    }
    s[t] = sum;
    __syncthreads();
    #pragma unroll
    for (int off = 1; off < 256; off <<= 1) {
        int x = (t >= off) ? s[t - off] : 0;
        __syncthreads();
        s[t] += x;
        __syncthreads();
    }
    int run = s[t] - sum;
    if (t == 255) partials[b] = s[255];
    #pragma unroll
    for (int j = 0; j < 4; j++) {
        if (base + j < N) rowptr[base + j] = run;
        run += v[j];
    }
}

__global__ void scan2_kernel(int* __restrict__ partials, int nb)
{
    if (threadIdx.x == 0 && blockIdx.x == 0) {
        int acc = 0;
        for (int i = 0; i < nb; i++) { int p = partials[i]; partials[i] = acc; acc += p; }
    }
}

__global__ void scan3_kernel(int* __restrict__ rowptr, const int* __restrict__ partials,
                             int* __restrict__ cursor, int N, int E)
{
    int i = blockIdx.x * blockDim.x + threadIdx.x;
    if (i < N) {
        int r = rowptr[i] + partials[i >> 10];
        rowptr[i] = r;
        cursor[i] = r;
    }
    if (i == 0) rowptr[N] = E;
}

__global__ void scatter_kernel(const int* __restrict__ src, const int* __restrict__ dst,
                               int* __restrict__ cursor, int* __restrict__ sorted_src, int E)
{
    int i = blockIdx.x * blockDim.x + threadIdx.x;
    if (i < E) {
        int pos = atomicAdd(cursor + __ldg(dst + i), 1);
        sorted_src[pos] = __ldg(src + i);
    }
}

// ================= GEMM1 fused with gather-1 =================
// Gather: 2 rows per warp (16 lanes x float4 each), MLP-8 batched neighbor loads.
// Then 64x128 register-tiled GEMM + relu.
__global__ __launch_bounds__(256) void gemm1_fused_kernel(const float* __restrict__ x,
                                                          const int* __restrict__ rowptr,
                                                          const int* __restrict__ sorted_src,
                                                          const float* __restrict__ W1,
                                                          const float* __restrict__ b1,
                                                          float* __restrict__ h,
                                                          int N)
{
    __shared__ float As[64][64];      // 16 KB, mean rows
    __shared__ float Ws[64][128];     // 32 KB
    int tid = threadIdx.x;
    int node0 = blockIdx.x * 64;
    int wid = tid >> 5, lane = tid & 31;
    int hlane = lane & 15, half = lane >> 4;

    // load W1: 8192 floats = 2048 float4, 8 per thread
    #pragma unroll
    for (int i = 0; i < 8; i++) {
        int lin = tid + i * 256;
        ((float4*)Ws)[lin] = ((const float4*)W1)[lin];
    }

    // gather: pass over 16 rows at a time (8 warps x 2 rows)
    #pragma unroll
    for (int pass = 0; pass < 4; pass++) {
        int row = pass * 16 + wid * 2 + half;
        int node = node0 + row;
        float4 acc = make_float4(0.f, 0.f, 0.f, 0.f);
        int beg = 0, end = 0;
        if (node < N) { beg = __ldg(rowptr + node); end = __ldg(rowptr + node + 1); }
        for (int e = beg; e < end; e += 8) {
            int s[8];
            #pragma unroll
            for (int j = 0; j < 8; j++)
                s[j] = __ldg(sorted_src + min(e + j, end - 1));
            float4 v[8];
            #pragma unroll
            for (int j = 0; j < 8; j++)
                v[j] = ((const float4*)x)[s[j] * 16 + hlane];
            #pragma unroll
            for (int j = 0; j < 8; j++)
                if (e + j < end) {
                    acc.x += v[j].x; acc.y += v[j].y;
                    acc.z += v[j].z; acc.w += v[j].w;
                }
        }
        float inv = 1.0f / ((float)(end - beg) + EPS);
        acc.x *= inv; acc.y *= inv; acc.z *= inv; acc.w *= inv;
        *(float4*)&As[row][hlane * 4] = acc;
    }
    __syncthreads();

    int tx = tid & 31, ty = tid >> 5;
    int col0 = tx * 4, row0 = ty * 8;
    float4 acc[8];
    float4 bias = *(const float4*)(b1 + col0);
    #pragma unroll
    for (int r = 0; r < 8; r++) acc[r] = bias;

    #pragma unroll 4
    for (int k = 0; k < 64; k++) {
        float4 w = *(float4*)&Ws[k][col0];
        #pragma unroll
        for (int r = 0; r < 8; r++) {
            float m = As[row0 + r][k];
            acc[r].x = fmaf(m, w.x, acc[r].x);
            acc[r].y = fmaf(m, w.y, acc[r].y);
            acc[r].z = fmaf(m, w.z, acc[r].z);
            acc[r].w = fmaf(m, w.w, acc[r].w);
        }
    }

    #pragma unroll
    for (int r = 0; r < 8; r++) {
        int node = node0 + row0 + r;
        if (node < N) {
            float4 o;
            o.x = fmaxf(acc[r].x, 0.f);
            o.y = fmaxf(acc[r].y, 0.f);
            o.z = fmaxf(acc[r].z, 0.f);
            o.w = fmaxf(acc[r].w, 0.f);
            *(float4*)(h + node * F2 + col0) = o;
        }
    }
}

// ================= GEMM2a: t = h @ W2 =================
__global__ __launch_bounds__(256) void gemm2a_kernel(const float* __restrict__ h,
                                                     const float* __restrict__ W2,
                                                     float* __restrict__ t,
                                                     int N)
{
    __shared__ float Ws[128][64];     // 32 KB, full W2
    __shared__ float As[64][64];      // 16 KB, K-chunk of h
    int tid = threadIdx.x;
    int node0 = blockIdx.x * 64;

    #pragma unroll
    for (int i = 0; i < 8; i++) {
        int lin = tid + i * 256;
        ((float4*)Ws)[lin] = ((const float4*)W2)[lin];
    }

    int tx = tid & 15, ty = tid >> 4;
    int col0 = tx * 4, row0 = ty * 4;
    float4 acc[4];
    #pragma unroll
    for (int r = 0; r < 4; r++) acc[r] = make_float4(0.f, 0.f, 0.f, 0.f);

    #pragma unroll
    for (int kc = 0; kc < 128; kc += 64) {
        __syncthreads();
        #pragma unroll
        for (int i = 0; i < 4; i++) {
            int lin = tid + i * 256;
            int row = lin >> 4;
            int kq  = lin & 15;
            int node = node0 + row;
            float4 v = make_float4(0.f, 0.f, 0.f, 0.f);
            if (node < N)
                v = ((const float4*)h)[node * 32 + (kc >> 2) + kq];
            ((float4*)As)[lin] = v;
        }
        __syncthreads();

        #pragma unroll 4
        for (int k = 0; k < 64; k++) {
            float4 w = *(float4*)&Ws[kc + k][col0];
            #pragma unroll
            for (int r = 0; r < 4; r++) {
                float m = As[row0 + r][k];
                acc[r].x = fmaf(m, w.x, acc[r].x);
                acc[r].y = fmaf(m, w.y, acc[r].y);
                acc[r].z = fmaf(m, w.z, acc[r].z);
                acc[r].w = fmaf(m, w.w, acc[r].w);
            }
        }
    }

    #pragma unroll
    for (int r = 0; r < 4; r++) {
        int node = node0 + row0 + r;
        if (node < N)
            *(float4*)(t + node * F3 + col0) = acc[r];
    }
}

// ================= gather-2 + bias + log_softmax =================
// 2 nodes per warp: 16 lanes x float4 per node, MLP-8 batched loads,
// half-warp shuffle reductions for log_softmax.
__global__ __launch_bounds__(256) void gather2_final_kernel(const float* __restrict__ t,
                                                            const int* __restrict__ rowptr,
                                                            const int* __restrict__ sorted_src,
                                                            const float* __restrict__ b2,
                                                            float* __restrict__ out,
                                                            int N)
{
    int tid = threadIdx.x;
    int wid = tid >> 5, lane = tid & 31;
    int hlane = lane & 15, half = lane >> 4;
    int node = blockIdx.x * 16 + wid * 2 + half;
    if (node >= N) return;

    int beg = __ldg(rowptr + node);
    int end = __ldg(rowptr + node + 1);
    float4 acc = make_float4(0.f, 0.f, 0.f, 0.f);
    for (int e = beg; e < end; e += 8) {
        int s[8];
        #pragma unroll
        for (int j = 0; j < 8; j++)
            s[j] = __ldg(sorted_src + min(e + j, end - 1));
        float4 v[8];
        #pragma unroll
        for (int j = 0; j < 8; j++)
            v[j] = ((const float4*)t)[s[j] * 16 + hlane];
        #pragma unroll
        for (int j = 0; j < 8; j++)
            if (e + j < end) {
                acc.x += v[j].x; acc.y += v[j].y;
                acc.z += v[j].z; acc.w += v[j].w;
            }
    }
    float inv = 1.0f / ((float)(end - beg) + EPS);
    float4 bb = ((const float4*)b2)[hlane];
    float4 v;
    v.x = acc.x * inv + bb.x;
    v.y = acc.y * inv + bb.y;
    v.z = acc.z * inv + bb.z;
    v.w = acc.w * inv + bb.w;

    // max over 64 cols: local 4, then half-warp (offsets 8,4,2,1 stay in half)
    float m = fmaxf(fmaxf(v.x, v.y), fmaxf(v.z, v.w));
    #pragma unroll
    for (int o = 8; o > 0; o >>= 1)
        m = fmaxf(m, __shfl_xor_sync(0xffffffffu, m, o));
    float s = expf(v.x - m) + expf(v.y - m) + expf(v.z - m) + expf(v.w - m);
    #pragma unroll
    for (int o = 8; o > 0; o >>= 1)
        s += __shfl_xor_sync(0xffffffffu, s, o);
    float l = m + logf(s);

    float4 o4 = make_float4(v.x - l, v.y - l, v.z - l, v.w - l);
    ((float4*)out)[node * 16 + hlane] = o4;
}

extern "C" void kernel_launch(void* const* d_in, const int* in_sizes, int n_in,
                              void* d_out, int out_size)
{
    const float* x   = (const float*)d_in[0];
    const int*   src = (const int*)d_in[1];
    const int*   dst = (const int*)d_in[2];
    const float* W1  = (const float*)d_in[3];
    const float* b1  = (const float*)d_in[4];
    const float* W2  = (const float*)d_in[5];
    const float* b2  = (const float*)d_in[6];
    float* out = (float*)d_out;

    int N = in_sizes[0] / F1;
    int E = in_sizes[1];

    float *h, *t;
    int *counts, *rowptr, *cursor, *partials, *sorted_src;
    cudaGetSymbolAddress((void**)&h, g_h);
    cudaGetSymbolAddress((void**)&t, g_t);
    cudaGetSymbolAddress((void**)&counts, g_counts);
    cudaGetSymbolAddress((void**)&rowptr, g_rowptr);
    cudaGetSymbolAddress((void**)&cursor, g_cursor);
    cudaGetSymbolAddress((void**)&partials, g_partials);
    cudaGetSymbolAddress((void**)&sorted_src, g_sorted_src);

    // ---- CSR build ----
    cudaMemsetAsync(counts, 0, (size_t)N * sizeof(int), 0);
    hist_kernel<<<(E + 255) / 256, 256, 0, 0>>>(dst, counts, E);
    int nb = (N + 1023) / 1024;
    scan1_kernel<<<nb, 256, 0, 0>>>(counts, rowptr, partials, N);
    scan2_kernel<<<1, 32, 0, 0>>>(partials, nb);
    scan3_kernel<<<(N + 255) / 256, 256, 0, 0>>>(rowptr, partials, cursor, N, E);
    scatter_kernel<<<(E + 255) / 256, 256, 0, 0>>>(src, dst, cursor, sorted_src, E);

    // ---- layer 1: gather(mean) + W1 + b1 + relu ----
    gemm1_fused_kernel<<<(N + 63) / 64, 256, 0, 0>>>(x, rowptr, sorted_src, W1, b1, h, N);

    // ---- t = h @ W2 (transform before aggregation) ----
    gemm2a_kernel<<<(N + 63) / 64, 256, 0, 0>>>(h, W2, t, N);

    // ---- layer 2: gather(mean) + b2 + log_softmax ----
    gather2_final_kernel<<<(N + 15) / 16, 256, 0, 0>>>(t, rowptr, sorted_src, b2, out, N);
}

// round 6
// speedup vs baseline: 2.3678x; 1.1083x over previous
#include <cuda_runtime.h>
#include <cuda_bf16.h>
#include <math.h>

#define MAXN 50000
#define MAXE 800000
#define F1 64      // nfeat
#define F2 128     // nhid
#define F3 64      // nclass
#define EPS 1e-6f

// ---------------- scratch (no allocation allowed) ----------------
__device__ __align__(16) float g_t[MAXN * F3];      // 12.8 MB: relu(h) @ W2
__device__ int g_counts[MAXN];
__device__ int g_rowptr[MAXN + 1];
__device__ int g_cursor[MAXN];
__device__ int g_partials[64];
__device__ int g_sorted_src[MAXE];                   // src ids grouped by dst

// ================= CSR build =================
__global__ void hist_kernel(const int* __restrict__ dst, int* __restrict__ counts, int E)
{
    int i = blockIdx.x * blockDim.x + threadIdx.x;
    if (i < E) atomicAdd(counts + __ldg(dst + i), 1);
}

// block = 256 threads, 1024 elements per block
__global__ void scan1_kernel(const int* __restrict__ counts, int* __restrict__ rowptr,
                             int* __restrict__ partials, int N)
{
    __shared__ int s[256];
    int b = blockIdx.x, t = threadIdx.x;
    int base = b * 1024 + t * 4;
    int v[4]; int sum = 0;
    #pragma unroll
    for (int j = 0; j < 4; j++) {
        v[j] = (base + j < N) ? counts[base + j] : 0;
        sum += v[j];
    }
    s[t] = sum;
    __syncthreads();
    #pragma unroll
    for (int off = 1; off < 256; off <<= 1) {
        int x = (t >= off) ? s[t - off] : 0;
        __syncthreads();
        s[t] += x;
        __syncthreads();
    }
    int run = s[t] - sum;
    if (t == 255) partials[b] = s[255];
    #pragma unroll
    for (int j = 0; j < 4; j++) {
        if (base + j < N) rowptr[base + j] = run;
        run += v[j];
    }
}

// merged scan2+scan3: each block locally prefix-sums the (<=64) block partials
__global__ void scan23_kernel(int* __restrict__ rowptr, const int* __restrict__ partials,
                              int* __restrict__ cursor, int nb, int N, int E)
{
    __shared__ int sp[64];
    int t = threadIdx.x;
    int orig = 0;
    if (t < 64) {
        orig = (t < nb) ? partials[t] : 0;
        sp[t] = orig;
    }
    __syncthreads();
    #pragma unroll
    for (int off = 1; off < 64; off <<= 1) {
        int x = (t < 64 && t >= off) ? sp[t - off] : 0;
        __syncthreads();
        if (t < 64) sp[t] += x;
        __syncthreads();
    }
    if (t < 64) sp[t] -= orig;     // exclusive
    __syncthreads();

    int i = blockIdx.x * blockDim.x + t;
    if (i < N) {
        int r = rowptr[i] + sp[i >> 10];
        rowptr[i] = r;
        cursor[i] = r;
    }
    if (i == 0) rowptr[N] = E;
}

__global__ void scatter_kernel(const int* __restrict__ src, const int* __restrict__ dst,
                               int* __restrict__ cursor, int* __restrict__ sorted_src, int E)
{
    int i = blockIdx.x * blockDim.x + threadIdx.x;
    if (i < E) {
        int pos = atomicAdd(cursor + __ldg(dst + i), 1);
        sorted_src[pos] = __ldg(src + i);
    }
}

// ================= Fused: gather-1 + GEMM1 + relu + GEMM2 =================
// Per 64-node block:
//   A) gather CSR mean of x into As[64][64]; load W1 into Ws[64][128]
//   B) GEMM1: 64x128 register tile (8 rows x 4 cols / thread) + bias
//   C) relu'd tile -> Hs (reusing Ws storage); t = Hs @ W2 in two 64-K chunks
//      (W2 chunks streamed through the As storage); write t.
// h never touches global memory.
__global__ __launch_bounds__(256) void fused12_kernel(const float* __restrict__ x,
                                                      const int* __restrict__ rowptr,
                                                      const int* __restrict__ sorted_src,
                                                      const float* __restrict__ W1,
                                                      const float* __restrict__ b1,
                                                      const float* __restrict__ W2,
                                                      float* __restrict__ t,
                                                      int N)
{
    __shared__ float sbuf[64 * 128 + 64 * 64];   // 48 KB
    float (*Ws)[128] = (float(*)[128])sbuf;                  // W1, then Hs
    float (*As)[64]  = (float(*)[64])(sbuf + 64 * 128);      // mean tile, then W2 chunks

    int tid = threadIdx.x;
    int node0 = blockIdx.x * 64;
    int wid = tid >> 5, lane = tid & 31;
    int hlane = lane & 15, half = lane >> 4;

    // ---- A: load W1 (2048 float4, 8/thread) ----
    #pragma unroll
    for (int i = 0; i < 8; i++) {
        int lin = tid + i * 256;
        ((float4*)Ws)[lin] = ((const float4*)W1)[lin];
    }

    // ---- A: gather means, 2 rows/warp, 16 lanes x float4, MLP-8 ----
    #pragma unroll
    for (int pass = 0; pass < 4; pass++) {
        int row = pass * 16 + wid * 2 + half;
        int node = node0 + row;
        float4 acc = make_float4(0.f, 0.f, 0.f, 0.f);
        int beg = 0, end = 0;
        if (node < N) { beg = __ldg(rowptr + node); end = __ldg(rowptr + node + 1); }
        for (int e = beg; e < end; e += 8) {
            int s[8];
            #pragma unroll
            for (int j = 0; j < 8; j++)
                s[j] = __ldg(sorted_src + min(e + j, end - 1));
            float4 v[8];
            #pragma unroll
            for (int j = 0; j < 8; j++)
                v[j] = ((const float4*)x)[s[j] * 16 + hlane];
            #pragma unroll
            for (int j = 0; j < 8; j++)
                if (e + j < end) {
                    acc.x += v[j].x; acc.y += v[j].y;
                    acc.z += v[j].z; acc.w += v[j].w;
                }
        }
        float inv = 1.0f / ((float)(end - beg) + EPS);
        acc.x *= inv; acc.y *= inv; acc.z *= inv; acc.w *= inv;
        *(float4*)&As[row][hlane * 4] = acc;
    }
    __syncthreads();

    // ---- B: GEMM1 (64x128), 8 rows x 4 cols per thread ----
    int tx = tid & 31, ty = tid >> 5;
    int col0 = tx * 4, row0 = ty * 8;
    float4 acc[8];
    float4 bias = *(const float4*)(b1 + col0);
    #pragma unroll
    for (int r = 0; r < 8; r++) acc[r] = bias;

    #pragma unroll 4
    for (int k = 0; k < 64; k++) {
        float4 w = *(float4*)&Ws[k][col0];
        #pragma unroll
        for (int r = 0; r < 8; r++) {
            float m = As[row0 + r][k];
            acc[r].x = fmaf(m, w.x, acc[r].x);
            acc[r].y = fmaf(m, w.y, acc[r].y);
            acc[r].z = fmaf(m, w.z, acc[r].z);
            acc[r].w = fmaf(m, w.w, acc[r].w);
        }
    }
    __syncthreads();     // S1: everyone done reading Ws/As

    // ---- C: relu -> Hs (Ws storage); load W2 chunk 0 into As ----
    #pragma unroll
    for (int r = 0; r < 8; r++) {
        float4 o;
        o.x = fmaxf(acc[r].x, 0.f);
        o.y = fmaxf(acc[r].y, 0.f);
        o.z = fmaxf(acc[r].z, 0.f);
        o.w = fmaxf(acc[r].w, 0.f);
        *(float4*)&Ws[row0 + r][col0] = o;
    }
    #pragma unroll
    for (int i = 0; i < 4; i++) {
        int lin = tid + i * 256;
        ((float4*)As)[lin] = ((const float4*)W2)[lin];          // chunk 0
    }

    int tx2 = tid & 15, ty2 = tid >> 4;
    int c0 = tx2 * 4, r0 = ty2 * 4;
    float4 acc2[4];
    #pragma unroll
    for (int r = 0; r < 4; r++) acc2[r] = make_float4(0.f, 0.f, 0.f, 0.f);

    #pragma unroll
    for (int c = 0; c < 2; c++) {
        if (c == 1) {
            __syncthreads();     // S3: chunk-0 reads done
            #pragma unroll
            for (int i = 0; i < 4; i++) {
                int lin = tid + i * 256;
                ((float4*)As)[lin] = ((const float4*)W2)[1024 + lin];   // chunk 1
            }
        }
        __syncthreads();         // S2 / S4
        #pragma unroll 4
        for (int k = 0; k < 64; k++) {
            float4 w = *(float4*)&As[k][c0];
            #pragma unroll
            for (int r = 0; r < 4; r++) {
                float m = Ws[r0 + r][c * 64 + k];
                acc2[r].x = fmaf(m, w.x, acc2[r].x);
                acc2[r].y = fmaf(m, w.y, acc2[r].y);
                acc2[r].z = fmaf(m, w.z, acc2[r].z);
                acc2[r].w = fmaf(m, w.w, acc2[r].w);
            }
        }
    }

    #pragma unroll
    for (int r = 0; r < 4; r++) {
        int node = node0 + r0 + r;
        if (node < N)
            *(float4*)(t + node * F3 + c0) = acc2[r];
    }
}

// ================= gather-2 + bias + log_softmax =================
// 2 nodes per warp: 16 lanes x float4 per node, MLP-8 batched loads,
// half-warp shuffle reductions for log_softmax.
__global__ __launch_bounds__(256) void gather2_final_kernel(const float* __restrict__ t,
                                                            const int* __restrict__ rowptr,
                                                            const int* __restrict__ sorted_src,
                                                            const float* __restrict__ b2,
                                                            float* __restrict__ out,
                                                            int N)
{
    int tid = threadIdx.x;
    int wid = tid >> 5, lane = tid & 31;
    int hlane = lane & 15, half = lane >> 4;
    int node = blockIdx.x * 16 + wid * 2 + half;
    if (node >= N) return;

    int beg = __ldg(rowptr + node);
    int end = __ldg(rowptr + node + 1);
    float4 acc = make_float4(0.f, 0.f, 0.f, 0.f);
    for (int e = beg; e < end; e += 8) {
        int s[8];
        #pragma unroll
        for (int j = 0; j < 8; j++)
            s[j] = __ldg(sorted_src + min(e + j, end - 1));
        float4 v[8];
        #pragma unroll
        for (int j = 0; j < 8; j++)
            v[j] = ((const float4*)t)[s[j] * 16 + hlane];
        #pragma unroll
        for (int j = 0; j < 8; j++)
            if (e + j < end) {
                acc.x += v[j].x; acc.y += v[j].y;
                acc.z += v[j].z; acc.w += v[j].w;
            }
    }
    float inv = 1.0f / ((float)(end - beg) + EPS);
    float4 bb = ((const float4*)b2)[hlane];
    float4 v;
    v.x = acc.x * inv + bb.x;
    v.y = acc.y * inv + bb.y;
    v.z = acc.z * inv + bb.z;
    v.w = acc.w * inv + bb.w;

    float m = fmaxf(fmaxf(v.x, v.y), fmaxf(v.z, v.w));
    #pragma unroll
    for (int o = 8; o > 0; o >>= 1)
        m = fmaxf(m, __shfl_xor_sync(0xffffffffu, m, o));
    float s = expf(v.x - m) + expf(v.y - m) + expf(v.z - m) + expf(v.w - m);
    #pragma unroll
    for (int o = 8; o > 0; o >>= 1)
        s += __shfl_xor_sync(0xffffffffu, s, o);
    float l = m + logf(s);

    float4 o4 = make_float4(v.x - l, v.y - l, v.z - l, v.w - l);
    ((float4*)out)[node * 16 + hlane] = o4;
}

extern "C" void kernel_launch(void* const* d_in, const int* in_sizes, int n_in,
                              void* d_out, int out_size)
{
    const float* x   = (const float*)d_in[0];
    const int*   src = (const int*)d_in[1];
    const int*   dst = (const int*)d_in[2];
    const float* W1  = (const float*)d_in[3];
    const float* b1  = (const float*)d_in[4];
    const float* W2  = (const float*)d_in[5];
    const float* b2  = (const float*)d_in[6];
    float* out = (float*)d_out;

    int N = in_sizes[0] / F1;
    int E = in_sizes[1];

    float *t;
    int *counts, *rowptr, *cursor, *partials, *sorted_src;
    cudaGetSymbolAddress((void**)&t, g_t);
    cudaGetSymbolAddress((void**)&counts, g_counts);
    cudaGetSymbolAddress((void**)&rowptr, g_rowptr);
    cudaGetSymbolAddress((void**)&cursor, g_cursor);
    cudaGetSymbolAddress((void**)&partials, g_partials);
    cudaGetSymbolAddress((void**)&sorted_src, g_sorted_src);

    // ---- CSR build ----
    cudaMemsetAsync(counts, 0, (size_t)N * sizeof(int), 0);
    hist_kernel<<<(E + 255) / 256, 256, 0, 0>>>(dst, counts, E);
    int nb = (N + 1023) / 1024;
    scan1_kernel<<<nb, 256, 0, 0>>>(counts, rowptr, partials, N);
    scan23_kernel<<<(N + 255) / 256, 256, 0, 0>>>(rowptr, partials, cursor, nb, N, E);
    scatter_kernel<<<(E + 255) / 256, 256, 0, 0>>>(src, dst, cursor, sorted_src, E);

    // ---- layers 1+2a fused: gather(mean) -> W1+b1+relu -> @W2 -> t ----
    fused12_kernel<<<(N + 63) / 64, 256, 0, 0>>>(x, rowptr, sorted_src, W1, b1, W2, t, N);

    // ---- layer 2b: gather(mean) + b2 + log_softmax ----
    gather2_final_kernel<<<(N + 15) / 16, 256, 0, 0>>>(t, rowptr, sorted_src, b2, out, N);
}